// round 10
// baseline (speedup 1.0000x reference)
#include <cuda_runtime.h>
#include <math.h>

#define NBLK1 4096
#define LOG2E 1.44269504088896f

__device__ __align__(16) float g_ypre[4194304];   // (b,h,w,c)
__device__ float g_part[NBLK1 * 8];
__device__ float g_stats[32];

// shared-memory float offsets
#define OFF_WIN   0        // [32][128]
#define OFF_WX    4096     // [64][34]
#define OFF_WOUT  6272     // [64][32]
#define OFF_WDT   8320     // [2][64]
#define OFF_BDT2  8448     // [64]
#define OFF_DS2   8512     // [64]
#define OFF_XF    8576     // [32][33] = 1056
#define OFF_XP    9632     // [32][66]  (aliased by YS; per-thread read-before-write)
#define OFF_YS    9632
#define OFF_GZ    11744    // [32][64]
#define OFF_B     13792    // [32][16]
#define OFF_C     14304    // [32][16]
#define OFF_DTSR  14816    // [32][2]
#define OFF_GACC  14880    // [32][2]
#define SMEM_FLOATS 14944  // 59776 B

__device__ __forceinline__ float ex2f(float x) {
    float y; asm("ex2.approx.ftz.f32 %0, %1;" : "=f"(y) : "f"(x)); return y;
}
__device__ __forceinline__ float softplusf(float v) {
    float e = __expf(v);
    return (v < -3.0f) ? e * (1.0f - e * (0.5f - 0.33333334f * e)) : log1pf(e);
}
__device__ __forceinline__ float geluf(float v) {
    return 0.5f * v * (1.0f + erff(v * 0.70710678118f));
}

__global__ __launch_bounds__(256, 2) void k1_main(
    const float* __restrict__ x, const float* __restrict__ W_in,
    const float* __restrict__ W_x, const float* __restrict__ W_dt,
    const float* __restrict__ b_dt, const float* __restrict__ A_logs,
    const float* __restrict__ Ds, const float* __restrict__ W_out)
{
    extern __shared__ float S[];
    const int tid = threadIdx.x;
    const int bid = blockIdx.x;

    // ---------------- weights to smem ----------------
    for (int i = tid; i < 4096; i += 256) S[OFF_WIN + i] = W_in[i];
    for (int i = tid; i < 2176; i += 256) S[OFF_WX + i] = W_x[i];
    for (int i = tid; i < 2048; i += 256) S[OFF_WOUT + i] = W_out[i];
    if (tid < 128) S[OFF_WDT + tid] = W_dt[tid];
    if (tid < 64) {
        S[OFF_BDT2 + tid] = 2.0f * b_dt[tid];
        S[OFF_DS2 + tid]  = 2.0f * Ds[tid];
    }
    int ok = 1;
    for (int i = tid; i < 1024; i += 256) {
        int n = i & 15;
        float ae = __expf(A_logs[i]);
        if (fabsf(ae - (float)(n + 1)) > 1e-3f * (float)(n + 1)) ok = 0;
    }

    // ---------------- x tile (4 consecutive w positions) ----------------
    const int m0 = bid * 4;
    {
        int b = m0 >> 12;
        int h = (m0 >> 6) & 63;
        int w0 = m0 & 63;
        const float* xb = x + b * (256 * 4096) + h * 64 + w0;
        for (int i = tid; i < 1024; i += 256) {
            int c = i >> 2, p = i & 3;
            int t = c >> 5, g = c & 31;
            S[OFF_XF + (p * 8 + t) * 33 + g] = xb[c * 4096 + p];
        }
    }
    const int fast = __syncthreads_and(ok);

    // ---------------- GEMM1: [32x32]@[32x128] -> xp(0..63) | gelu(z)(64..127) -------
    {
        const int row = tid >> 3, cg = tid & 7;
        float acc[16];
        #pragma unroll
        for (int j = 0; j < 16; j++) acc[j] = 0.0f;
        const float4* W4 = reinterpret_cast<const float4*>(&S[OFF_WIN]);
        #pragma unroll 4
        for (int k = 0; k < 32; k++) {
            float a = S[OFF_XF + row * 33 + k];
            const float4* wr = W4 + k * 32 + cg * 4;
            #pragma unroll
            for (int q = 0; q < 4; q++) {
                float4 w = wr[q];
                acc[4*q+0] = fmaf(a, w.x, acc[4*q+0]);
                acc[4*q+1] = fmaf(a, w.y, acc[4*q+1]);
                acc[4*q+2] = fmaf(a, w.z, acc[4*q+2]);
                acc[4*q+3] = fmaf(a, w.w, acc[4*q+3]);
            }
        }
        if (cg < 4) {
            #pragma unroll
            for (int j = 0; j < 16; j++)
                S[OFF_XP + row * 66 + cg * 16 + j] = acc[j];
        } else {
            int c0 = (cg - 4) * 16;
            #pragma unroll
            for (int j = 0; j < 16; j++)
                S[OFF_GZ + row * 64 + c0 + j] = geluf(acc[j]);
        }
    }
    __syncthreads();

    // ---------------- GEMM2: [32x64]@[64x34] -> dts(0,1)|B(2..17)|C(18..33) ---------
    {
        const int rq = tid >> 3, cq = tid & 7;
        float acc[4];
        acc[0] = acc[1] = acc[2] = acc[3] = 0.0f;
        #pragma unroll 4
        for (int k = 0; k < 64; k++) {
            float a = S[OFF_XP + rq * 66 + k];
            const float* wp = &S[OFF_WX + k * 34 + 4 * cq];
            acc[0] = fmaf(a, wp[0], acc[0]);
            acc[1] = fmaf(a, wp[1], acc[1]);
            acc[2] = fmaf(a, wp[2], acc[2]);
            acc[3] = fmaf(a, wp[3], acc[3]);
        }
        #pragma unroll
        for (int j = 0; j < 4; j++) {
            int col = 4 * cq + j;
            if (col < 2)       S[OFF_DTSR + rq * 2 + col] = acc[j];
            else if (col < 18) S[OFF_B + rq * 16 + (col - 2)] = acc[j];
            else               S[OFF_C + rq * 16 + (col - 18)] = acc[j];
        }
        if (tid < 64) {
            // cols 32,33 -> C[14],C[15]
            int r = tid >> 1;
            int j = 32 + (tid & 1);
            float a2 = 0.0f;
            #pragma unroll 8
            for (int k = 0; k < 64; k++)
                a2 = fmaf(S[OFF_XP + r * 66 + k], S[OFF_WX + k * 34 + j], a2);
            S[OFF_C + r * 16 + (j - 18)] = a2;
        }
    }
    __syncthreads();

    // ------- bidirectional selective scan: 1 d-lane per thread -------
    {
        const int p = tid >> 6;     // position 0..3
        const int d = tid & 63;     // lane 0..63
        float du[8], rra[8];
        float h[16];
        #pragma unroll
        for (int n = 0; n < 16; n++) h[n] = 0.0f;

        if (fast) {
            // forward
            #pragma unroll
            for (int t = 0; t < 8; t++) {
                int r = p * 8 + t;
                float q0 = S[OFF_DTSR + r * 2];
                float q1 = S[OFF_DTSR + r * 2 + 1];
                float v = fmaf(q0, S[OFF_WDT + d], fmaf(q1, S[OFF_WDT + 64 + d], S[OFF_BDT2 + d]));
                float sp = softplusf(v);
                float u = S[OFF_XP + r * 66 + d];
                float rr = ex2f(-sp * LOG2E);
                du[t] = sp * u;
                rra[t] = rr;
                float a = rr, y = 0.0f;
                #pragma unroll
                for (int n = 0; n < 16; n++) {
                    float Bn = S[OFF_B + r * 16 + n];
                    float Cn = S[OFF_C + r * 16 + n];
                    h[n] = fmaf(a, h[n], du[t] * Bn);
                    y = fmaf(h[n], Cn, y);
                    if (n < 15) a *= rr;
                }
                S[OFF_YS + r * 66 + d] = fmaf(u, S[OFF_DS2 + d], y);
            }
            // backward + gate (latched du/rr only)
            #pragma unroll
            for (int n = 0; n < 16; n++) h[n] = 0.0f;
            #pragma unroll
            for (int t = 7; t >= 0; t--) {
                int r = p * 8 + t;
                float rr = rra[t];
                float a = rr, y = 0.0f;
                #pragma unroll
                for (int n = 0; n < 16; n++) {
                    float Bn = S[OFF_B + r * 16 + n];
                    float Cn = S[OFF_C + r * 16 + n];
                    h[n] = fmaf(a, h[n], du[t] * Bn);
                    y = fmaf(h[n], Cn, y);
                    if (n < 15) a *= rr;
                }
                S[OFF_YS + r * 66 + d] = (S[OFF_YS + r * 66 + d] + y) * S[OFF_GZ + r * 64 + d];
            }
        } else {
            // slow fallback: decays from gmem A_logs (rra holds softplus)
            #pragma unroll 1
            for (int t = 0; t < 8; t++) {
                int r = p * 8 + t;
                float q0 = S[OFF_DTSR + r * 2];
                float q1 = S[OFF_DTSR + r * 2 + 1];
                float sp = softplusf(fmaf(q0, S[OFF_WDT + d], fmaf(q1, S[OFF_WDT + 64 + d], S[OFF_BDT2 + d])));
                float u = S[OFF_XP + r * 66 + d];
                du[t] = sp * u;
                rra[t] = sp;
                float y = 0.0f;
                #pragma unroll 1
                for (int n = 0; n < 16; n++) {
                    float Bn = S[OFF_B + r * 16 + n];
                    float Cn = S[OFF_C + r * 16 + n];
                    float a = __expf(-sp * __expf(__ldg(&A_logs[d * 16 + n])));
                    h[n] = fmaf(a, h[n], du[t] * Bn);
                    y = fmaf(h[n], Cn, y);
                }
                S[OFF_YS + r * 66 + d] = fmaf(u, S[OFF_DS2 + d], y);
            }
            #pragma unroll
            for (int n = 0; n < 16; n++) h[n] = 0.0f;
            #pragma unroll 1
            for (int t = 7; t >= 0; t--) {
                int r = p * 8 + t;
                float sp = rra[t];
                float y = 0.0f;
                #pragma unroll 1
                for (int n = 0; n < 16; n++) {
                    float Bn = S[OFF_B + r * 16 + n];
                    float Cn = S[OFF_C + r * 16 + n];
                    float a = __expf(-sp * __expf(__ldg(&A_logs[d * 16 + n])));
                    h[n] = fmaf(a, h[n], du[t] * Bn);
                    y = fmaf(h[n], Cn, y);
                }
                S[OFF_YS + r * 66 + d] = (S[OFF_YS + r * 66 + d] + y) * S[OFF_GZ + r * 64 + d];
            }
        }
    }
    __syncthreads();

    // ---------------- GEMM3: [32x64]@[64x32] -> y_pre + group partials ----------------
    {
        const int row = tid >> 3, cq = tid & 7;
        float acc[4];
        acc[0] = acc[1] = acc[2] = acc[3] = 0.0f;
        const float4* W4 = reinterpret_cast<const float4*>(&S[OFF_WOUT]);
        #pragma unroll 4
        for (int k = 0; k < 64; k++) {
            float a = S[OFF_YS + row * 66 + k];
            float4 w = W4[k * 8 + cq];
            acc[0] = fmaf(a, w.x, acc[0]);
            acc[1] = fmaf(a, w.y, acc[1]);
            acc[2] = fmaf(a, w.z, acc[2]);
            acc[3] = fmaf(a, w.w, acc[3]);
        }
        int p = row >> 3, t = row & 7;
        *reinterpret_cast<float4*>(&g_ypre[(m0 + p) * 256 + t * 32 + 4 * cq]) =
            make_float4(acc[0], acc[1], acc[2], acc[3]);
        float s  = acc[0] + acc[1] + acc[2] + acc[3];
        float ss = acc[0]*acc[0] + acc[1]*acc[1] + acc[2]*acc[2] + acc[3]*acc[3];
        #pragma unroll
        for (int off = 4; off; off >>= 1) {
            s  += __shfl_down_sync(0xffffffffu, s,  off, 8);
            ss += __shfl_down_sync(0xffffffffu, ss, off, 8);
        }
        if ((tid & 7) == 0) {
            S[OFF_GACC + row * 2]     = s;
            S[OFF_GACC + row * 2 + 1] = ss;
        }
    }
    __syncthreads();
    if (tid < 8) {
        int g = tid & 3, hh = tid >> 2;
        float v = 0.0f;
        #pragma unroll
        for (int q = 0; q < 4; q++) {
            v += S[OFF_GACC + (q * 8 + 2 * g) * 2 + hh];
            v += S[OFF_GACC + (q * 8 + 2 * g + 1) * 2 + hh];
        }
        g_part[bid * 8 + g * 2 + hh] = v;
    }
}

// ---------------- kernel 2: partials -> 16 stats ----------------
__global__ void k2_stats() {
    __shared__ float ssum[256], ssq[256];
    int b = blockIdx.x >> 2, g = blockIdx.x & 3;
    int tid = threadIdx.x;
    float s = 0.0f, q = 0.0f;
    for (int j = tid; j < 1024; j += 256) {
        int blk = b * 1024 + j;
        s += g_part[blk * 8 + g * 2];
        q += g_part[blk * 8 + g * 2 + 1];
    }
    ssum[tid] = s; ssq[tid] = q;
    __syncthreads();
    for (int st = 128; st; st >>= 1) {
        if (tid < st) { ssum[tid] += ssum[tid + st]; ssq[tid] += ssq[tid + st]; }
        __syncthreads();
    }
    if (tid == 0) {
        float invN = 1.0f / 262144.0f;
        float mean = ssum[0] * invN;
        float var  = ssq[0] * invN - mean * mean;
        g_stats[blockIdx.x * 2]     = mean;
        g_stats[blockIdx.x * 2 + 1] = rsqrtf(var + 1e-5f);
    }
}

// ---------------- kernel 3: groupnorm affine + transpose + residual ----------------
__global__ __launch_bounds__(256) void k3_final(
    const float* __restrict__ x, const float* __restrict__ gn_w,
    const float* __restrict__ gn_b, float* __restrict__ out)
{
    __shared__ float sm[32][33];
    int tx = threadIdx.x, ty = threadIdx.y;
    int ct = blockIdx.x & 7, wt = blockIdx.x >> 3;
    int h = blockIdx.y, b = blockIdx.z;
    int c0 = ct * 32, w0 = wt * 32;
    int c = c0 + tx;
    int grp = c >> 6;
    float mean = g_stats[(b * 4 + grp) * 2];
    float rsig = g_stats[(b * 4 + grp) * 2 + 1];
    float gw = gn_w[c], gb = gn_b[c];
    const float* yp = g_ypre + ((b * 64 + h) * 64 + w0) * 256;
    #pragma unroll
    for (int i = 0; i < 4; i++) {
        int wl = ty + 8 * i;
        float v = yp[wl * 256 + c];
        sm[wl][tx] = fmaf((v - mean) * rsig, gw, gb);
    }
    __syncthreads();
    #pragma unroll
    for (int i = 0; i < 4; i++) {
        int cl = ty + 8 * i;
        int gi = ((b * 256 + c0 + cl) * 64 + h) * 64 + w0 + tx;
        out[gi] = x[gi] + sm[tx][cl];
    }
}

extern "C" void kernel_launch(void* const* d_in, const int* in_sizes, int n_in,
                              void* d_out, int out_size) {
    const float* x      = (const float*)d_in[0];
    const float* W_in   = (const float*)d_in[1];
    const float* W_x    = (const float*)d_in[2];
    const float* W_dt   = (const float*)d_in[3];
    const float* b_dt   = (const float*)d_in[4];
    const float* A_logs = (const float*)d_in[5];
    const float* Ds     = (const float*)d_in[6];
    const float* W_out  = (const float*)d_in[7];
    const float* gn_w   = (const float*)d_in[8];
    const float* gn_b   = (const float*)d_in[9];
    float* out = (float*)d_out;

    cudaFuncSetAttribute(k1_main, cudaFuncAttributeMaxDynamicSharedMemorySize,
                         SMEM_FLOATS * 4);
    k1_main<<<NBLK1, 256, SMEM_FLOATS * 4>>>(x, W_in, W_x, W_dt, b_dt, A_logs, Ds, W_out);
    k2_stats<<<16, 256>>>();
    k3_final<<<dim3(16, 64, 4), dim3(32, 8)>>>(x, gn_w, gn_b, out);
}